// round 3
// baseline (speedup 1.0000x reference)
#include <cuda_runtime.h>
#include <cuda_bf16.h>
#include <math.h>

#define BN 64
#define CN 64
#define KN 1024
#define NPTS 65536            // B*H*W points
#define PLANE 1024            // H*W
#define ZSZ 4194304           // B*C*H*W
#define EPSV 1e-10f
#define MARGIN 3.5e-3f
#define RINGSZ 8
#define LISTCAP 12

typedef unsigned long long ull;

__device__ float          g_cnorm[KN];
__device__ int            g_hist[KN];
__device__ __nv_bfloat16  g_cbbf[KN * CN];

// ---------------------------------------------------------------------------
// prep: exact codebook norms (sequential chain), bf16 codebook, zero hist
// ---------------------------------------------------------------------------
__global__ void k_prep(const float* __restrict__ cb) {
    int k = blockIdx.x * blockDim.x + threadIdx.x;
    if (k >= KN) return;
    const float* row = cb + k * CN;
    float s = 0.0f;
    #pragma unroll
    for (int c = 0; c < CN; c++) {
        float e = row[c];
        s = __fadd_rn(s, __fmul_rn(e, e));
        g_cbbf[k * CN + c] = __float2bfloat16(e);
    }
    g_cnorm[k] = s;
    g_hist[k] = 0;
}

// ---------------------------------------------------------------------------
// helpers
// ---------------------------------------------------------------------------
__device__ __forceinline__ void mma16816(float& d0, float& d1, float& d2, float& d3,
                                         unsigned a0, unsigned a1, unsigned a2, unsigned a3,
                                         unsigned b0, unsigned b1) {
    asm volatile(
        "mma.sync.aligned.m16n8k16.row.col.f32.bf16.bf16.f32 "
        "{%0,%1,%2,%3}, {%4,%5,%6,%7}, {%8,%9}, {%0,%1,%2,%3};"
        : "+f"(d0), "+f"(d1), "+f"(d2), "+f"(d3)
        : "r"(a0), "r"(a1), "r"(a2), "r"(a3), "r"(b0), "r"(b1));
}

// replace-max ring insert; tracks the minimum score ever evicted
__device__ __forceinline__ void ringIns(float s, int k, float* rs, int* rk, float& mev) {
    float mx = rs[0]; int im = 0;
    #pragma unroll
    for (int j = 1; j < RINGSZ; j++) if (rs[j] > mx) { mx = rs[j]; im = j; }
    if (s < mx) {
        mev = fminf(mev, mx);
        #pragma unroll
        for (int j = 0; j < RINGSZ; j++) if (j == im) { rs[j] = s; rk[j] = k; }
    } else {
        mev = fminf(mev, s);
    }
}

// exact reference-rounded distance: d = RN(RN(xn+en) + RN(-2*dot)), dot = seq fma chain
__device__ __forceinline__ float exactDist(const float* zp, const float* crow, float xn, float en) {
    float dot = 0.0f;
    #pragma unroll
    for (int c = 0; c < CN; c++) dot = __fmaf_rn(zp[c * PLANE], crow[c], dot);
    return __fadd_rn(__fadd_rn(xn, en), __fmul_rn(-2.0f, dot));
}

// ---------------------------------------------------------------------------
// main: bf16 split-x MMA prescreen -> exact recheck -> outputs
// CTA = 128 consecutive points (same b), 256 threads = 8 warps (16 pts each).
// ---------------------------------------------------------------------------
// dynamic smem layout (bytes):
#define SM_FBBEST   0                        // ull
#define SM_FBCNT    8                        // int
#define SM_ENORM    16                       // float[256]
#define SM_CANDCNT  1040                     // int[128]
#define SM_FBFLAG   1552                     // int[128]
#define SM_BESTS    2064                     // int[128]
#define SM_FBROWS   2576                     // int[128]
#define SM_CANDK    3088                     // int[128*12]
#define SM_CBS      9232                     // bf16, 256 rows x pitch 72  (36864B)
#define SM_XHI      46096                    // bf16, 128 rows x pitch 72  (18432B)
#define SM_XLO      64528                    // bf16, 128 rows x pitch 72  (18432B)
#define SM_TOTAL    82960

__global__ __launch_bounds__(256, 2)
void k_main(const float* __restrict__ z, const float* __restrict__ cb,
            float* __restrict__ out) {
    extern __shared__ char smem[];
    ull*   fbBest  = (ull*)(smem + SM_FBBEST);
    int*   fbCnt   = (int*)(smem + SM_FBCNT);
    float* enorm_s = (float*)(smem + SM_ENORM);
    int*   candCnt = (int*)(smem + SM_CANDCNT);
    int*   fbFlag  = (int*)(smem + SM_FBFLAG);
    int*   bests   = (int*)(smem + SM_BESTS);
    int*   fbRows  = (int*)(smem + SM_FBROWS);
    int*   candK   = (int*)(smem + SM_CANDK);
    unsigned*       cbs32 = (unsigned*)(smem + SM_CBS);
    __nv_bfloat16*  xhi   = (__nv_bfloat16*)(smem + SM_XHI);
    __nv_bfloat16*  xlo   = (__nv_bfloat16*)(smem + SM_XLO);
    const unsigned* xhi32 = (const unsigned*)(smem + SM_XHI);
    const unsigned* xlo32 = (const unsigned*)(smem + SM_XLO);

    const int tid  = threadIdx.x;
    const int lane = tid & 31;
    const int warp = tid >> 5;
    const int n0   = blockIdx.x * 128;                 // first point of CTA
    const float* zb = z + (size_t)(n0 >> 10) * (CN * PLANE) + (n0 & 1023);

    // ---- stage x tile (fp32 -> bf16 hi/lo, pitch 72), zero bookkeeping ----
    if (tid < 128) { candCnt[tid] = 0; fbFlag[tid] = 0; }
    if (tid == 0) { *fbCnt = 0; }
    for (int i = tid; i < 128 * 64; i += 256) {
        int c = i >> 7, p = i & 127;
        float x = zb[c * PLANE + p];
        __nv_bfloat16 hi = __float2bfloat16(x);
        __nv_bfloat16 lo = __float2bfloat16(x - __bfloat162float(hi));
        xhi[p * 72 + c] = hi;
        xlo[p * 72 + c] = lo;
    }
    __syncthreads();

    // ---- A fragments (held in regs for whole sweep) ----
    const int r = lane >> 2, t = lane & 3;
    const int m0 = warp * 16;
    unsigned ah[4][4], al[4][4];
    #pragma unroll
    for (int ch = 0; ch < 4; ch++) {
        int base0 = (m0 + r) * 36 + ch * 8 + t;
        int base1 = (m0 + r + 8) * 36 + ch * 8 + t;
        ah[ch][0] = xhi32[base0];     ah[ch][1] = xhi32[base1];
        ah[ch][2] = xhi32[base0 + 4]; ah[ch][3] = xhi32[base1 + 4];
        al[ch][0] = xlo32[base0];     al[ch][1] = xlo32[base1];
        al[ch][2] = xlo32[base0 + 4]; al[ch][3] = xlo32[base1 + 4];
    }

    // ---- per-(thread,row) prescreen state ----
    float rs0[RINGSZ], rs1[RINGSZ];
    int   rk0[RINGSZ], rk1[RINGSZ];
    #pragma unroll
    for (int j = 0; j < RINGSZ; j++) { rs0[j] = 1e30f; rs1[j] = 1e30f; rk0[j] = 0; rk1[j] = 0; }
    float rmin0 = 1e30f, rmin1 = 1e30f, mev0 = 1e30f, mev1 = 1e30f;

    // ---- sweep codebook in 4 chunks of 256 k ----
    for (int chn = 0; chn < 4; chn++) {
        const int kb0 = chn * 256;
        __syncthreads();
        {   // stage bf16 codebook chunk (pitch 72) + norms
            const unsigned* src = (const unsigned*)g_cbbf + (size_t)kb0 * 32;
            for (int i = tid; i < 256 * 32; i += 256) {
                int kr = i >> 5, c2 = i & 31;
                cbs32[kr * 36 + c2] = src[kr * 32 + c2];
            }
            if (tid < 256) enorm_s[tid] = g_cnorm[kb0 + tid];
        }
        __syncthreads();

        #pragma unroll 2
        for (int nt = 0; nt < 32; nt++) {
            const int kbrel = nt * 8;
            float d0 = 0.f, d1 = 0.f, d2 = 0.f, d3 = 0.f;
            const int brow = (kbrel + (lane >> 2)) * 36 + t;
            #pragma unroll
            for (int ch = 0; ch < 4; ch++) {
                unsigned b0 = cbs32[brow + ch * 8];
                unsigned b1 = cbs32[brow + ch * 8 + 4];
                mma16816(d0, d1, d2, d3, ah[ch][0], ah[ch][1], ah[ch][2], ah[ch][3], b0, b1);
                mma16816(d0, d1, d2, d3, al[ch][0], al[ch][1], al[ch][2], al[ch][3], b0, b1);
            }
            float2 en = *(const float2*)&enorm_s[kbrel + 2 * t];
            const int k0 = kb0 + kbrel + 2 * t;
            float s0 = __fmaf_rn(-2.0f, d0, en.x);   // row r,   k0
            float s1 = __fmaf_rn(-2.0f, d1, en.y);   // row r,   k0+1
            float s2 = __fmaf_rn(-2.0f, d2, en.x);   // row r+8, k0
            float s3 = __fmaf_rn(-2.0f, d3, en.y);   // row r+8, k0+1
            if (s0 < rmin0 + MARGIN) ringIns(s0, k0,     rs0, rk0, mev0);
            if (s1 < rmin0 + MARGIN) ringIns(s1, k0 + 1, rs0, rk0, mev0);
            if (s2 < rmin1 + MARGIN) ringIns(s2, k0,     rs1, rk1, mev1);
            if (s3 < rmin1 + MARGIN) ringIns(s3, k0 + 1, rs1, rk1, mev1);
            rmin0 = fminf(rmin0, fminf(s0, s1));
            rmin1 = fminf(rmin1, fminf(s2, s3));
        }
    }

    // ---- quad reduction + candidate emission ----
    {
        float g0 = rmin0, g1 = rmin1;
        g0 = fminf(g0, __shfl_xor_sync(0xffffffffu, g0, 1));
        g0 = fminf(g0, __shfl_xor_sync(0xffffffffu, g0, 2));
        g1 = fminf(g1, __shfl_xor_sync(0xffffffffu, g1, 1));
        g1 = fminf(g1, __shfl_xor_sync(0xffffffffu, g1, 2));
        const int row0 = m0 + r, row1 = m0 + r + 8;
        float thr0 = g0 + MARGIN, thr1 = g1 + MARGIN;
        if (mev0 <= thr0) atomicOr(&fbFlag[row0], 1);
        if (mev1 <= thr1) atomicOr(&fbFlag[row1], 1);
        #pragma unroll
        for (int j = 0; j < RINGSZ; j++) {
            if (rs0[j] <= thr0) {
                int pos = atomicAdd(&candCnt[row0], 1);
                if (pos < LISTCAP) candK[row0 * LISTCAP + pos] = rk0[j];
                else atomicOr(&fbFlag[row0], 1);
            }
            if (rs1[j] <= thr1) {
                int pos = atomicAdd(&candCnt[row1], 1);
                if (pos < LISTCAP) candK[row1 * LISTCAP + pos] = rk1[j];
                else atomicOr(&fbFlag[row1], 1);
            }
        }
    }
    __syncthreads();

    // ---- phase 2: exact recheck per point ----
    if (tid < 128) {
        const int row = tid;
        if (fbFlag[row]) {
            int pos = atomicAdd(fbCnt, 1);
            fbRows[pos] = row;
        } else {
            const float* zp = zb + row;
            float xn = 0.0f;
            #pragma unroll
            for (int c = 0; c < CN; c++) {
                float x = zp[c * PLANE];
                xn = __fadd_rn(xn, __fmul_rn(x, x));
            }
            int cnt = candCnt[row]; if (cnt > LISTCAP) cnt = LISTCAP;
            float bestd = 1e30f; int bk = 0x7fffffff;
            for (int j = 0; j < cnt; j++) {
                int k = candK[row * LISTCAP + j];
                float d = exactDist(zp, cb + (size_t)k * CN, xn, g_cnorm[k]);
                if (d < bestd || (d == bestd && k < bk)) { bestd = d; bk = k; }
            }
            bests[row] = bk;
            out[(size_t)2 * ZSZ + n0 + row] = (float)bk;
            atomicAdd(&g_hist[bk], 1);
        }
    }
    __syncthreads();

    // ---- phase 2.5: warp-cooperative fallback (provably-safe net, ~never) ----
    const int nfb = *fbCnt;
    for (int f = 0; f < nfb; f++) {
        const int row = fbRows[f];
        __syncthreads();
        if (tid == 0) *fbBest = ~0ull;
        __syncthreads();
        const float* zp = zb + row;
        float xn = 0.0f;
        #pragma unroll
        for (int c = 0; c < CN; c++) {
            float x = zp[c * PLANE];
            xn = __fadd_rn(xn, __fmul_rn(x, x));
        }
        for (int k = tid; k < KN; k += 256) {
            float d = exactDist(zp, cb + (size_t)k * CN, xn, g_cnorm[k]);
            ull pk = ((ull)__float_as_uint(d) << 32) | (unsigned)k;  // d > 0 always
            atomicMin(fbBest, pk);
        }
        __syncthreads();
        if (tid == 0) {
            int bk = (int)(*fbBest & 0xffffffffull);
            bests[row] = bk;
            out[(size_t)2 * ZSZ + n0 + row] = (float)bk;
            atomicAdd(&g_hist[bk], 1);
        }
    }
    __syncthreads();

    // ---- phase 3: gather + quantized / straight-through outputs (coalesced) ----
    const size_t obase = (size_t)(n0 >> 10) * (CN * PLANE) + (n0 & 1023);
    for (int i = tid; i < 128 * 64; i += 256) {
        int c = i >> 7, p = i & 127;
        int k = bests[p];
        float q = cb[(size_t)k * CN + c];
        float x = zb[c * PLANE + p];
        size_t o = obase + (size_t)c * PLANE + p;
        out[o]       = q;
        out[o + ZSZ] = __fadd_rn(x, __fsub_rn(q, x));   // z + (q - z)
    }
}

// ---------------------------------------------------------------------------
// perplexity
// ---------------------------------------------------------------------------
__global__ void k_perp(float* __restrict__ out) {
    __shared__ float red[32];
    int t = threadIdx.x;
    float p = (float)g_hist[t] * (1.0f / (float)NPTS);
    float term = __fmul_rn(p, logf(fmaxf(p, EPSV)));
    #pragma unroll
    for (int o = 16; o; o >>= 1) term += __shfl_xor_sync(0xffffffffu, term, o);
    if ((t & 31) == 0) red[t >> 5] = term;
    __syncthreads();
    if (t < 32) {
        float s = red[t];
        #pragma unroll
        for (int o = 16; o; o >>= 1) s += __shfl_xor_sync(0xffffffffu, s, o);
        if (t == 0) out[(size_t)2 * ZSZ + NPTS] = expf(-s);
    }
}

// ---------------------------------------------------------------------------
extern "C" void kernel_launch(void* const* d_in, const int* in_sizes, int n_in,
                              void* d_out, int out_size) {
    const float* z  = (const float*)d_in[0];
    const float* cb = (const float*)d_in[1];
    if (n_in >= 2 && in_sizes[0] == KN * CN && in_sizes[1] == ZSZ) {
        const float* tmp = z; z = cb; cb = tmp;
    }
    float* out = (float*)d_out;

    cudaFuncSetAttribute(k_main, cudaFuncAttributeMaxDynamicSharedMemorySize, SM_TOTAL);

    k_prep<<<4, 256>>>(cb);
    k_main<<<512, 256, SM_TOTAL>>>(z, cb, out);
    k_perp<<<1, 1024>>>(out);
    (void)out_size;
}